// round 8
// baseline (speedup 1.0000x reference)
#include <cuda_runtime.h>
#include <stdint.h>

#define N1 12800          // 100*128 elements of tm1
#define N2 25600          // 100*256 elements of tm2
#define NT 38400
#define K1 6399           // (N1-1)//2 -> torch lower-median rank
#define K2 12799
#define NBLOCKS 150
#define TPB 256           // 150*256 == 38400 exactly, 1 elem/thread
#define R 4               // replicas (atomic-chain splitting)
#define CAPR 256          // per-replica bucket capacity
#define SMALL 512         // fast-path limit on selected-bin population

// -------- device scratch (reset in-kernel every run) ----------------------
// replica-adjacent: 4 counters of one bin form one uint4/float4
__device__ unsigned int g_bcnt [2][2048][R];      // count hists
__device__ float        g_whist[2][2048][R];      // weight hists
__device__ uint2        g_bkt  [2][2048][R][CAPR];// packed {key, w} buckets
__device__ double       g_sum_p1, g_sum_p2;       // sum (t - vmask)^2
__device__ double       g_sum_a1, g_sum_a2;       // sum amask^2
__device__ unsigned int g_arrive;

__device__ __forceinline__ unsigned int mono(unsigned int u) {
    return u ^ ((unsigned int)((int)u >> 31) | 0x80000000u);
}

// re-derive gathered value (fallback only)
__device__ __forceinline__ float regather(int a2, int idx,
                                          const float* c2, const float* c3)
{
    return a2 == 0 ? c2[(size_t)idx * 3136 + 399]
                   : c3[(size_t)idx * 784  + 87];
}

// ------------- fallback-only: 256-thread block select ---------------------
__device__ unsigned int block_select256(const unsigned int* hist, int nb,
                                        unsigned int* warpbuf,
                                        unsigned int* k_sh, unsigned int* sel_sh)
{
    int tid  = threadIdx.x;
    int lane = tid & 31;
    int warp = tid >> 5;          // 0..7
    int bpt  = nb >> 8;           // 8 or 4
    int base = tid * bpt;

    unsigned int local = 0;
    for (int j = 0; j < bpt; j++) local += hist[base + j];

    unsigned int incl = local;
    #pragma unroll
    for (int o = 1; o < 32; o <<= 1) {
        unsigned int t = __shfl_up_sync(0xffffffffu, incl, o);
        if (lane >= o) incl += t;
    }
    if (lane == 31) warpbuf[warp] = incl;
    __syncthreads();

    unsigned int woff = 0;
    for (int w = 0; w < warp; w++) woff += warpbuf[w];
    unsigned int ex = woff + incl - local;
    unsigned int k  = *k_sh;
    __syncthreads();

    unsigned int c = ex;
    for (int j = 0; j < bpt; j++) {
        unsigned int h = hist[base + j];
        if (k >= c && k < c + h) {
            *sel_sh = (unsigned int)(base + j);
            *k_sh   = k - c;
        }
        c += h;
    }
    __syncthreads();
    return *sel_sh;
}

__device__ float block_sum256(float v, float* redf)
{
    int lane = threadIdx.x & 31;
    int warp = threadIdx.x >> 5;
    #pragma unroll
    for (int o = 16; o; o >>= 1) v += __shfl_down_sync(0xffffffffu, v, o);
    if (lane == 0) redf[warp] = v;
    __syncthreads();
    float r = 0.f;
    if (threadIdx.x == 0) {
        #pragma unroll
        for (int w = 0; w < 8; w++) r += redf[w];
        redf[0] = r;
    }
    __syncthreads();
    r = redf[0];
    __syncthreads();
    return r;
}

// ---------------------------------------------------------------------------
__global__ void __launch_bounds__(TPB) fused_kernel(
    const float* __restrict__ c2,  const float* __restrict__ c3,
    const float* __restrict__ vm1, const float* __restrict__ vm2,
    const float* __restrict__ am1, const float* __restrict__ am2,
    float* __restrict__ out)
{
    __shared__ unsigned int wt_c[2][4];
    __shared__ float        wt_w[2][4];
    __shared__ unsigned int d0_sh[2], kin_sh[2];
    __shared__ float        suf_sh[2];
    __shared__ unsigned int rc_sh[2][R];
    __shared__ unsigned int sk[2][SMALL];
    __shared__ float        sw[2][SMALL];
    __shared__ unsigned int mkey_sh[2];
    __shared__ float        S_sh[2];
    __shared__ unsigned int ovf_sh[2];
    __shared__ unsigned int fb_hist[2048];
    __shared__ unsigned int warpbuf[8];
    __shared__ float        redf[8];
    __shared__ unsigned int k_sh, sel_sh;
    __shared__ float        shp1[8], shp2[8], sha1[8], sha2[8];
    __shared__ bool         is_last_sh;

    int tid  = threadIdx.x;
    int lane = tid & 31;
    int warp = tid >> 5;

    // ===================== gather: exactly 1 element/thread =================
    int e = blockIdx.x * TPB + tid;      // always < NT (150*256 == 38400)
    float t, v, a;
    int arr;
    if (e < N1) {
        t = c2[(size_t)e * 3136 + 399];              // [.,.,7,7]: 7*56+7
        v = vm1[e]; a = am1[e]; arr = 0;
    } else {
        int idx = e - N1;
        t = c3[(size_t)idx * 784 + 87];              // [.,.,3,3]: 3*28+3
        v = vm2[idx]; a = am2[idx]; arr = 1;
    }
    unsigned int key = mono(__float_as_uint(t));
    float w = 1.0f - 2.0f * a;
    unsigned int bin = key >> 21;
    int rr = blockIdx.x & (R - 1);
    unsigned int pos = atomicAdd(&g_bcnt[arr][bin][rr], 1u);
    if (pos < CAPR)
        g_bkt[arr][bin][rr][pos] = make_uint2(key, __float_as_uint(w));
    atomicAdd(&g_whist[arr][bin][rr], w);            // no return -> RED

    float d = t - v;
    float p1 = 0.f, p2 = 0.f, a1s = 0.f, a2s = 0.f;
    if (arr == 0) { p1 = d * d; a1s = a * a; }
    else          { p2 = d * d; a2s = a * a; }
    #pragma unroll
    for (int o = 16; o; o >>= 1) {
        p1  += __shfl_down_sync(0xffffffffu, p1,  o);
        p2  += __shfl_down_sync(0xffffffffu, p2,  o);
        a1s += __shfl_down_sync(0xffffffffu, a1s, o);
        a2s += __shfl_down_sync(0xffffffffu, a2s, o);
    }
    if (lane == 0) { shp1[warp] = p1; shp2[warp] = p2;
                     sha1[warp] = a1s; sha2[warp] = a2s; }
    __syncthreads();

    if (tid == 0) {
        float x1 = 0.f, x2 = 0.f, x3 = 0.f, x4 = 0.f;
        #pragma unroll
        for (int j = 0; j < 8; j++) {
            x1 += shp1[j]; x2 += shp2[j]; x3 += sha1[j]; x4 += sha2[j];
        }
        atomicAdd(&g_sum_p1, (double)x1);
        atomicAdd(&g_sum_p2, (double)x2);
        atomicAdd(&g_sum_a1, (double)x3);
        atomicAdd(&g_sum_a2, (double)x4);
        __threadfence();
        unsigned int r2 = atomicAdd(&g_arrive, 1u);
        is_last_sh = (r2 == (unsigned int)(NBLOCKS - 1));
    }
    __syncthreads();
    if (!is_last_sh) return;

    // ===================== finalize (last block only) =======================
    double sp1 = __ldcg(&g_sum_p1);
    double sp2 = __ldcg(&g_sum_p2);
    double sa1 = __ldcg(&g_sum_a1);
    double sa2 = __ldcg(&g_sum_a2);

    int half    = tid >> 7;          // 0/1 == array
    int htid    = tid & 127;
    int hwarp   = htid >> 5;         // 0..3
    int karr    = half;
    int binbase = htid << 4;         // 16 bins per thread

    // ---- trip 1: sum replica hists per bin (vector loads, L1-cached)
    unsigned int cnt[16];
    float        wsm[16];
    unsigned int lc = 0; float lw = 0.f;
    #pragma unroll
    for (int j = 0; j < 16; j++) {
        uint4  c4 = *reinterpret_cast<const uint4*>(&g_bcnt[karr][binbase + j][0]);
        float4 w4 = *reinterpret_cast<const float4*>(&g_whist[karr][binbase + j][0]);
        cnt[j] = c4.x + c4.y + c4.z + c4.w;
        wsm[j] = w4.x + w4.y + w4.z + w4.w;
        lc += cnt[j]; lw += wsm[j];
    }

    // ---- fused select + suffix weight (1 barrier for warp totals)
    unsigned int ic = lc; float iw = lw;
    #pragma unroll
    for (int o = 1; o < 32; o <<= 1) {
        unsigned int tc = __shfl_up_sync(0xffffffffu, ic, o);
        float        tw = __shfl_up_sync(0xffffffffu, iw, o);
        if (lane >= o) { ic += tc; iw += tw; }
    }
    if (lane == 31) { wt_c[half][hwarp] = ic; wt_w[half][hwarp] = iw; }
    __syncthreads();

    unsigned int woff_c = 0; float woff_w = 0.f, total_w = 0.f;
    #pragma unroll
    for (int w2 = 0; w2 < 4; w2++) {
        unsigned int cc = wt_c[half][w2];
        float        ww = wt_w[half][w2];
        if (w2 < hwarp) { woff_c += cc; woff_w += ww; }
        total_w += ww;
    }
    unsigned int ex  = woff_c + (ic - lc);
    float        exw = woff_w + (iw - lw);
    unsigned int K   = karr ? K2 : K1;
    {
        unsigned int c = ex; float wp = exw;
        #pragma unroll
        for (int j = 0; j < 16; j++) {
            if (K >= c && K < c + cnt[j]) {
                d0_sh[half]  = (unsigned int)(binbase + j);
                kin_sh[half] = K - c;
                suf_sh[half] = total_w - (wp + wsm[j]);
            }
            c += cnt[j]; wp += wsm[j];
        }
    }
    __syncthreads();

    // ---- owning thread re-reads its bin's replica counts (L1 hit)
    unsigned int d0 = d0_sh[half];
    if (htid == (int)(d0 >> 4)) {
        uint4 c4 = *reinterpret_cast<const uint4*>(&g_bcnt[karr][d0][0]);
        rc_sh[half][0] = c4.x; rc_sh[half][1] = c4.y;
        rc_sh[half][2] = c4.z; rc_sh[half][3] = c4.w;
        unsigned int nc = c4.x + c4.y + c4.z + c4.w;
        ovf_sh[half] = (nc > SMALL || c4.x > CAPR || c4.y > CAPR ||
                        c4.z > CAPR || c4.w > CAPR) ? 1u : 0u;
    }
    __syncthreads();

    // ---- reset hists (values consumed; fire-and-forget vector stores)
    const uint4  z4 = {0u, 0u, 0u, 0u};
    const float4 zf = {0.f, 0.f, 0.f, 0.f};
    #pragma unroll
    for (int j = 0; j < 16; j++) {
        *reinterpret_cast<uint4*>(&g_bcnt[karr][binbase + j][0])   = z4;
        *reinterpret_cast<float4*>(&g_whist[karr][binbase + j][0]) = zf;
    }

    if (!(ovf_sh[0] | ovf_sh[1])) {
        // =============== fast path: small-set median, halves concurrent ====
        unsigned int kin = kin_sh[half];
        unsigned int o1 = rc_sh[half][0];
        unsigned int o2 = o1 + rc_sh[half][1];
        unsigned int o3 = o2 + rc_sh[half][2];
        unsigned int nc = o3 + rc_sh[half][3];

        // trip 2: bucket data (<=4 packed elements per thread)
        #pragma unroll
        for (int k = 0; k < 4; k++) {
            int p = htid + (k << 7);
            if (p < (int)nc) {
                int r3, q;
                if      (p >= (int)o3) { r3 = 3; q = p - (int)o3; }
                else if (p >= (int)o2) { r3 = 2; q = p - (int)o2; }
                else if (p >= (int)o1) { r3 = 1; q = p - (int)o1; }
                else                   { r3 = 0; q = p; }
                uint2 kv = __ldcg(&g_bkt[karr][d0][r3][q]);
                sk[half][p] = kv.x;
                sw[half][p] = __uint_as_float(kv.y);
            }
        }
        __syncthreads();
        #pragma unroll
        for (int k = 0; k < 4; k++) {
            int p = htid + (k << 7);
            if (p < (int)nc) {
                unsigned int mykey = sk[half][p];
                unsigned int less = 0, eq = 0;
                for (unsigned int j = 0; j < nc; j++) {
                    unsigned int kj = sk[half][j];
                    less += (kj < mykey);
                    eq   += (kj == mykey);
                }
                if (less <= kin && kin < less + eq) mkey_sh[half] = mykey;
            }
        }
        __syncthreads();
        unsigned int mkey = mkey_sh[half];
        float s = 0.f;
        #pragma unroll
        for (int k = 0; k < 4; k++) {
            int p = htid + (k << 7);
            if (p < (int)nc && sk[half][p] >= mkey) s += sw[half][p];
        }
        #pragma unroll
        for (int o = 16; o; o >>= 1) s += __shfl_down_sync(0xffffffffu, s, o);
        if (lane == 0) wt_w[half][hwarp] = s;
        __syncthreads();
        if (htid == 0) {
            float tsum = wt_w[half][0] + wt_w[half][1] +
                         wt_w[half][2] + wt_w[half][3];
            S_sh[half] = suf_sh[half] + tsum;
        }
    } else {
        // =============== fallback: recompute from inputs (block-wide) ======
        __syncthreads();
        for (int a2 = 0; a2 < 2; a2++) {
            unsigned int fd0 = d0_sh[a2];
            int n = a2 ? N2 : N1;
            const float* am = a2 ? am2 : am1;
            if (tid == 0) k_sh = kin_sh[a2];
            for (int b = tid; b < 2048; b += TPB) fb_hist[b] = 0u;
            __syncthreads();
            for (int j = tid; j < n; j += TPB) {
                unsigned int kk = mono(__float_as_uint(regather(a2, j, c2, c3)));
                if ((kk >> 21) == fd0) atomicAdd(&fb_hist[(kk >> 10) & 2047u], 1u);
            }
            __syncthreads();
            unsigned int d1 = block_select256(fb_hist, 2048, warpbuf, &k_sh, &sel_sh);
            unsigned int p21 = (fd0 << 11) | d1;
            for (int b = tid; b < 1024; b += TPB) fb_hist[b] = 0u;
            __syncthreads();
            for (int j = tid; j < n; j += TPB) {
                unsigned int kk = mono(__float_as_uint(regather(a2, j, c2, c3)));
                if ((kk >> 10) == p21) atomicAdd(&fb_hist[kk & 1023u], 1u);
            }
            __syncthreads();
            unsigned int d2 = block_select256(fb_hist, 1024, warpbuf, &k_sh, &sel_sh);
            unsigned int mkey = (p21 << 10) | d2;
            float s = 0.f;
            for (int j = tid; j < n; j += TPB) {
                unsigned int kk = mono(__float_as_uint(regather(a2, j, c2, c3)));
                if ((kk >> 21) == fd0 && kk >= mkey) s += 1.0f - 2.0f * am[j];
            }
            s = block_sum256(s, redf);
            if (tid == 0) S_sh[a2] = suf_sh[a2] + s;
            __syncthreads();
        }
    }
    __syncthreads();

    // ===================== output + remaining state reset ===================
    if (tid == 0) {
        double p = (sqrt(sp1) + sqrt(sp2)) * (1.0 / 38400.0);
        double q1sq = sa1 + (double)S_sh[0];
        double q2sq = sa2 + (double)S_sh[1];
        double q = (sqrt(q1sq) + sqrt(q2sq)) * (1.0 / 384.0);
        out[0] = (float)p;
        out[1] = (float)q;
        g_sum_p1 = 0.0; g_sum_p2 = 0.0;
        g_sum_a1 = 0.0; g_sum_a2 = 0.0;
        g_arrive = 0u;
    }
}

// ---------------------------------------------------------------------------
extern "C" void kernel_launch(void* const* d_in, const int* in_sizes, int n_in,
                              void* d_out, int out_size)
{
    const float* c2  = (const float*)d_in[0];
    const float* c3  = (const float*)d_in[1];
    const float* vm1 = (const float*)d_in[2];
    const float* vm2 = (const float*)d_in[3];
    const float* am1 = (const float*)d_in[4];
    const float* am2 = (const float*)d_in[5];
    float* out = (float*)d_out;

    fused_kernel<<<NBLOCKS, TPB>>>(c2, c3, vm1, vm2, am1, am2, out);
}

// round 9
// speedup vs baseline: 1.2033x; 1.2033x over previous
#include <cuda_runtime.h>
#include <stdint.h>

#define N1 12800          // 100*128 elements of tm1
#define N2 25600          // 100*256 elements of tm2
#define NT 38400
#define K1 6399           // (N1-1)//2 -> torch lower-median rank
#define K2 12799
#define NBLOCKS 148
#define EPB 260           // 148*260 = 38480 >= 38400
#define CAP 2048          // per-bin bucket capacity
#define SMALL 512         // small-set selection threshold

// -------- device scratch (reset in-kernel every run) ----------------------
__device__ unsigned int g_bcnt[2][2048];          // count hists (= level-1)
__device__ float        g_whist[2][2048];         // weight hists
__device__ uint2        g_bkt[2 * 2048 * CAP];    // packed {key, w} buckets
__device__ double       g_sum_p1, g_sum_p2;       // sum (t - vmask)^2
__device__ double       g_sum_a1, g_sum_a2;       // sum amask^2
__device__ unsigned int g_arrive;

__device__ __forceinline__ unsigned int mono(unsigned int u) {
    return u ^ ((unsigned int)((int)u >> 31) | 0x80000000u);
}

// re-derive gathered value (fallback only)
__device__ __forceinline__ float regather(int a2, int idx,
                                          const float* c2, const float* c3)
{
    return a2 == 0 ? c2[(size_t)idx * 3136 + 399]
                   : c3[(size_t)idx * 784  + 87];
}

// ---------------------------------------------------------------------------
// Block-wide: find bin containing rank *k_sh in hist[0..nb); update *k_sh to
// rank-within-bin; return bin. blockDim.x == 1024, nb in {1024, 2048}.
// ---------------------------------------------------------------------------
__device__ unsigned int block_select(const unsigned int* hist, int nb,
                                     unsigned int* warpbuf,
                                     unsigned int* k_sh, unsigned int* sel_sh)
{
    int tid  = threadIdx.x;
    int lane = tid & 31;
    int warp = tid >> 5;
    int bpt  = nb >> 10;
    int base = tid * bpt;

    unsigned int local = 0;
    for (int j = 0; j < bpt; j++) local += hist[base + j];

    unsigned int incl = local;
    #pragma unroll
    for (int o = 1; o < 32; o <<= 1) {
        unsigned int t = __shfl_up_sync(0xffffffffu, incl, o);
        if (lane >= o) incl += t;
    }
    if (lane == 31) warpbuf[warp] = incl;
    __syncthreads();
    if (warp == 0) {
        unsigned int w = warpbuf[lane];
        unsigned int wi = w;
        #pragma unroll
        for (int o = 1; o < 32; o <<= 1) {
            unsigned int t = __shfl_up_sync(0xffffffffu, wi, o);
            if (lane >= o) wi += t;
        }
        warpbuf[lane] = wi - w;
    }
    __syncthreads();

    unsigned int ex = (incl - local) + warpbuf[warp];
    unsigned int k = *k_sh;
    __syncthreads();

    unsigned int c = ex;
    for (int j = 0; j < bpt; j++) {
        unsigned int h = hist[base + j];
        if (k >= c && k < c + h) {
            *sel_sh = (unsigned int)(base + j);
            *k_sh   = k - c;
        }
        c += h;
    }
    __syncthreads();
    return *sel_sh;
}

// block-wide float sum; all threads receive the result
__device__ float block_sum(float v, float* redf)
{
    int lane = threadIdx.x & 31;
    int warp = threadIdx.x >> 5;
    #pragma unroll
    for (int o = 16; o; o >>= 1) v += __shfl_down_sync(0xffffffffu, v, o);
    if (lane == 0) redf[warp] = v;
    __syncthreads();
    if (warp == 0) {
        float r = redf[lane];
        #pragma unroll
        for (int o = 16; o; o >>= 1) r += __shfl_down_sync(0xffffffffu, r, o);
        if (lane == 0) redf[0] = r;
    }
    __syncthreads();
    float r = redf[0];
    __syncthreads();
    return r;
}

// ---------------------------------------------------------------------------
__global__ void __launch_bounds__(1024) fused_kernel(
    const float* __restrict__ c2,  const float* __restrict__ c3,
    const float* __restrict__ vm1, const float* __restrict__ vm2,
    const float* __restrict__ am1, const float* __restrict__ am2,
    float* __restrict__ out)
{
    __shared__ unsigned int sh_cnt[2048];
    __shared__ float        sh_w[2048];
    __shared__ unsigned int sk[SMALL];
    __shared__ float        sw[SMALL];
    __shared__ unsigned int warpbuf[32];
    __shared__ float        redf[32];
    __shared__ unsigned int k_sh, sel_sh, mkey_sh;
    __shared__ bool         is_last;

    int tid  = threadIdx.x;
    int lane = tid & 31;

    // ===================== gather (all blocks, EPB elems each) ==============
    float p1 = 0.f, p2 = 0.f, a1s = 0.f, a2s = 0.f;
    int e = blockIdx.x * EPB + tid;
    if (tid < EPB && e < NT) {
        float t, v, a;
        int arr;
        if (e < N1) {
            t = c2[(size_t)e * 3136 + 399];         // [.,.,7,7]: 7*56+7
            v = vm1[e]; a = am1[e]; arr = 0;
        } else {
            int idx = e - N1;
            t = c3[(size_t)idx * 784 + 87];         // [.,.,3,3]: 3*28+3
            v = vm2[idx]; a = am2[idx]; arr = 1;
        }
        unsigned int key = mono(__float_as_uint(t));
        float w = 1.0f - 2.0f * a;
        unsigned int bin = key >> 21;
        unsigned int pos = atomicAdd(&g_bcnt[arr][bin], 1u);
        if (pos < CAP) {
            size_t slot = (size_t)(((unsigned)arr << 11) | bin) * CAP + pos;
            g_bkt[slot] = make_uint2(key, __float_as_uint(w));
        }
        atomicAdd(&g_whist[arr][bin], w);
        float d = t - v;
        if (arr == 0) { p1 = d * d; a1s = a * a; }
        else          { p2 = d * d; a2s = a * a; }
    }
    #pragma unroll
    for (int o = 16; o; o >>= 1) {
        p1  += __shfl_down_sync(0xffffffffu, p1,  o);
        p2  += __shfl_down_sync(0xffffffffu, p2,  o);
        a1s += __shfl_down_sync(0xffffffffu, a1s, o);
        a2s += __shfl_down_sync(0xffffffffu, a2s, o);
    }
    if (lane == 0) {
        if (p1  != 0.f) atomicAdd(&g_sum_p1, (double)p1);
        if (p2  != 0.f) atomicAdd(&g_sum_p2, (double)p2);
        if (a1s != 0.f) atomicAdd(&g_sum_a1, (double)a1s);
        if (a2s != 0.f) atomicAdd(&g_sum_a2, (double)a2s);
    }

    // ===================== grid arrival =====================================
    __threadfence();
    __syncthreads();
    if (tid == 0) {
        unsigned int r = atomicAdd(&g_arrive, 1u);
        is_last = (r == (unsigned int)(gridDim.x - 1));
    }
    __syncthreads();
    if (!is_last) return;

    // ===================== finalize (last block only) =======================
    double sp1 = __ldcg(&g_sum_p1);
    double sp2 = __ldcg(&g_sum_p2);
    double sa1 = __ldcg(&g_sum_a1);
    double sa2 = __ldcg(&g_sum_a2);

    float S[2];
    const unsigned int kranks[2] = {K1, K2};

    for (int arr = 0; arr < 2; arr++) {
        // ---- batched prefetch of cnt + weight hists into shared (high MLP)
        for (int b = tid; b < 2048; b += 1024) {
            sh_cnt[b] = __ldcg(&g_bcnt[arr][b]);
            sh_w[b]   = __ldcg(&g_whist[arr][b]);
        }
        if (tid == 0) k_sh = kranks[arr];
        __syncthreads();

        // ---- level 1: select bin holding the median rank
        unsigned int d0 = block_select(sh_cnt, 2048, warpbuf, &k_sh, &sel_sh);

        // suffix weight over bins strictly above d0
        float s1 = 0.f;
        for (int b = tid; b < 2048; b += 1024)
            if (b > (int)d0) s1 += sh_w[b];
        float Sx = block_sum(s1, redf);

        unsigned int nc = sh_cnt[d0];
        unsigned int k  = k_sh;                 // rank within bin
        __syncthreads();
        size_t slotbase = (size_t)(((unsigned)arr << 11) | d0) * CAP;

        if (nc <= SMALL) {
            // ======= small-set path (expected: nc ~ 10..50 for randn) =======
            if (tid < (int)nc) {
                uint2 kv = __ldcg(&g_bkt[slotbase + tid]);
                sk[tid] = kv.x;
                sw[tid] = __uint_as_float(kv.y);
            }
            __syncthreads();
            if (tid < (int)nc) {
                unsigned int key = sk[tid];
                unsigned int less = 0, eq = 0;
                for (unsigned int j = 0; j < nc; j++) {
                    unsigned int kj = sk[j];
                    less += (kj < key);
                    eq   += (kj == key);
                }
                if (less <= k && k < less + eq) mkey_sh = key;
            }
            __syncthreads();
            unsigned int mkey = mkey_sh;
            float s = (tid < (int)nc && sk[tid] >= mkey) ? sw[tid] : 0.f;
            Sx += block_sum(s, redf);
        } else if (nc <= CAP) {
            // ======= histogram path over the bucket =======
            unsigned int key0 = 0u, key1 = 0u;
            float        w0 = 0.f, w1 = 0.f;
            bool h0 = (tid < (int)nc), h1 = (tid + 1024 < (int)nc);
            if (h0) { uint2 kv = __ldcg(&g_bkt[slotbase + tid]);
                      key0 = kv.x; w0 = __uint_as_float(kv.y); }
            if (h1) { uint2 kv = __ldcg(&g_bkt[slotbase + tid + 1024]);
                      key1 = kv.x; w1 = __uint_as_float(kv.y); }
            // level 2: bits [20:10]
            for (int b = tid; b < 2048; b += 1024) sh_cnt[b] = 0u;
            __syncthreads();
            if (h0) atomicAdd(&sh_cnt[(key0 >> 10) & 2047u], 1u);
            if (h1) atomicAdd(&sh_cnt[(key1 >> 10) & 2047u], 1u);
            __syncthreads();
            unsigned int d1 = block_select(sh_cnt, 2048, warpbuf, &k_sh, &sel_sh);
            // level 3: bits [9:0]
            sh_cnt[tid] = 0u;
            __syncthreads();
            if (h0 && ((key0 >> 10) & 2047u) == d1) atomicAdd(&sh_cnt[key0 & 1023u], 1u);
            if (h1 && ((key1 >> 10) & 2047u) == d1) atomicAdd(&sh_cnt[key1 & 1023u], 1u);
            __syncthreads();
            unsigned int d2 = block_select(sh_cnt, 1024, warpbuf, &k_sh, &sel_sh);
            unsigned int mkey = (d0 << 21) | (d1 << 10) | d2;
            float s = 0.f;
            if (h0 && key0 >= mkey) s += w0;
            if (h1 && key1 >= mkey) s += w1;
            Sx += block_sum(s, redf);
        } else {
            // ======= fallback: bucket overflowed, recompute from inputs =====
            const float* am = arr ? am2 : am1;
            int n = arr ? N2 : N1;
            for (int b = tid; b < 2048; b += 1024) sh_cnt[b] = 0u;
            __syncthreads();
            for (int j = tid; j < n; j += 1024) {
                unsigned int key = mono(__float_as_uint(regather(arr, j, c2, c3)));
                if ((key >> 21) == d0) atomicAdd(&sh_cnt[(key >> 10) & 2047u], 1u);
            }
            __syncthreads();
            unsigned int d1 = block_select(sh_cnt, 2048, warpbuf, &k_sh, &sel_sh);
            unsigned int p21 = (d0 << 11) | d1;
            sh_cnt[tid] = 0u;
            __syncthreads();
            for (int j = tid; j < n; j += 1024) {
                unsigned int key = mono(__float_as_uint(regather(arr, j, c2, c3)));
                if ((key >> 10) == p21) atomicAdd(&sh_cnt[key & 1023u], 1u);
            }
            __syncthreads();
            unsigned int d2 = block_select(sh_cnt, 1024, warpbuf, &k_sh, &sel_sh);
            unsigned int mkey = (p21 << 10) | d2;
            float s = 0.f;
            for (int j = tid; j < n; j += 1024) {
                unsigned int key = mono(__float_as_uint(regather(arr, j, c2, c3)));
                if ((key >> 21) == d0 && key >= mkey) s += 1.0f - 2.0f * am[j];
            }
            Sx += block_sum(s, redf);
        }
        S[arr] = Sx;
    }

    // ===================== output + state reset =============================
    __syncthreads();
    for (int b = tid; b < 2048; b += 1024) {
        g_bcnt[0][b] = 0u;   g_bcnt[1][b] = 0u;
        g_whist[0][b] = 0.f; g_whist[1][b] = 0.f;
    }
    if (tid == 0) {
        double p = (sqrt(sp1) + sqrt(sp2)) * (1.0 / 38400.0);
        double q1sq = sa1 + (double)S[0];
        double q2sq = sa2 + (double)S[1];
        double q = (sqrt(q1sq) + sqrt(q2sq)) * (1.0 / 384.0);
        out[0] = (float)p;
        out[1] = (float)q;
        g_sum_p1 = 0.0; g_sum_p2 = 0.0;
        g_sum_a1 = 0.0; g_sum_a2 = 0.0;
        g_arrive = 0u;
    }
}

// ---------------------------------------------------------------------------
extern "C" void kernel_launch(void* const* d_in, const int* in_sizes, int n_in,
                              void* d_out, int out_size)
{
    const float* c2  = (const float*)d_in[0];
    const float* c3  = (const float*)d_in[1];
    const float* vm1 = (const float*)d_in[2];
    const float* vm2 = (const float*)d_in[3];
    const float* am1 = (const float*)d_in[4];
    const float* am2 = (const float*)d_in[5];
    float* out = (float*)d_out;

    fused_kernel<<<NBLOCKS, 1024>>>(c2, c3, vm1, vm2, am1, am2, out);
}